// round 16
// baseline (speedup 1.0000x reference)
#include <cuda_runtime.h>
#include <stdint.h>

// NeighborNoiser — partitionable threefry2x32, key (0,42), fold = x0^x1 (bit-exact R2+).
// R16: occupancy probe. R13's 39 regs came from neighbor float4s + row pointers
// held live across the ~1300-instr hash section. Reorder: 16 hash chains FIRST
// (needs ~12 live regs + 16 results), THEN recompute addresses, load neighbors,
// epilogue. Live-set ~30 -> launch_bounds(256,8) = 2048 thr/SM (occ ~100%).
// Target: alu busy 93.8 -> 97+%, dur -> ~238us. Spill signature = L1%/DRAM% jump.

#define N1 25165824u                    // 8*3*1024*1024

__device__ __forceinline__ uint32_t rotl(uint32_t v, const int d) {
    return __funnelshift_l(v, v, d);
}

#define RS(d) { x0 += x1; x1 = rotl(x1,(d)) ^ x0; }

// SHF-rotate threefry chain, IADD3-fused key schedule
__device__ __forceinline__ uint32_t tf_shf(uint32_t ctr) {
    const uint32_t ks1 = 42u, ks2 = 0x1BD11BDAu ^ 42u;
    uint32_t x1 = ctr + ks1;
    uint32_t x0 = x1;                               // round-1 add with x0 = 0
    x1 = rotl(x1,13) ^ x0;
    RS(15) RS(26) RS(6)
    x1 += ks2 + 1u;  x0 = x0 + x1 + ks1;  x1 = rotl(x1,17) ^ x0;
    RS(29) RS(16) RS(24)
    x1 += 2u;        x0 = x0 + x1 + ks2;  x1 = rotl(x1,13) ^ x0;
    RS(15) RS(26) RS(6)
    x1 += ks1 + 3u;  x0 = x0 + x1;        x1 = rotl(x1,17) ^ x0;   // ks0 = 0
    RS(29) RS(16) RS(24)
    x1 += ks2 + 4u;  x0 = x0 + x1 + ks1;  x1 = rotl(x1,13) ^ x0;
    RS(15) RS(26) RS(6)
    x1 += 5u;
    return (x0 + ks2) ^ x1;
}

// Single IMAD.HI (fma pipe): hi(bits * 2^23) + 0x3f800000 -> [1,2); then -1.
__device__ __forceinline__ float u01(uint32_t bits) {
    uint32_t m;
    asm("mad.hi.u32 %0, %1, %2, %3;"
        : "=r"(m) : "r"(bits), "r"(1u << 23), "r"(0x3f800000u));
    return __uint_as_float(m) - 1.0f;
}

__global__ __launch_bounds__(256, 8)
void neighbor_noiser_kernel(const float* __restrict__ t, float* __restrict__ out) {
    uint32_t gid  = blockIdx.x * blockDim.x + threadIdx.x;
    uint32_t base = gid * 4u;                   // 4 adjacent pixels in one row

    // ---- phase 1: all 16 hash chains (alu-dense, small live set) ----
    uint32_t bu0 = tf_shf(base);
    uint32_t bu1 = tf_shf(base + 1u);
    uint32_t bu2 = tf_shf(base + 2u);
    uint32_t bu3 = tf_shf(base + 3u);
    uint32_t bd0 = tf_shf(base + N1);
    uint32_t bd1 = tf_shf(base + N1 + 1u);
    uint32_t bd2 = tf_shf(base + N1 + 2u);
    uint32_t bd3 = tf_shf(base + N1 + 3u);
    uint32_t bl0 = tf_shf(base + 2u*N1);
    uint32_t bl1 = tf_shf(base + 2u*N1 + 1u);
    uint32_t bl2 = tf_shf(base + 2u*N1 + 2u);
    uint32_t bl3 = tf_shf(base + 2u*N1 + 3u);
    uint32_t br0 = tf_shf(base + 3u*N1);
    uint32_t br1 = tf_shf(base + 3u*N1 + 1u);
    uint32_t br2 = tf_shf(base + 3u*N1 + 2u);
    uint32_t br3 = tf_shf(base + 3u*N1 + 3u);

    // ---- phase 2: addresses recomputed here, loads issued late ----
    uint32_t plane = base >> 20;
    uint32_t pos   = base & 0xFFFFFu;
    uint32_t y     = pos >> 10;
    uint32_t x     = pos & 1023u;               // multiple of 4

    const float* p = t + ((size_t)plane << 20);
    uint32_t yu = (y == 0u)    ? 0u    : y - 1u;
    uint32_t yd = (y == 1023u) ? 1023u : y + 1u;
    const float* rowc = p + (y << 10);

    float4 up4 = __ldg((const float4*)(p + (yu << 10) + x));
    float4 dn4 = __ldg((const float4*)(p + (yd << 10) + x));
    float4 ct4 = __ldg((const float4*)(rowc + x));
    float lf_e = (x == 0u)     ? ct4.x : __ldg(rowc + x - 1u);
    float rt_e = (x == 1020u)  ? ct4.w : __ldg(rowc + x + 4u);

    // ---- phase 3: epilogues ----
    float upv[4] = {up4.x, up4.y, up4.z, up4.w};
    float dnv[4] = {dn4.x, dn4.y, dn4.z, dn4.w};
    float lfv[4] = {lf_e,  ct4.x, ct4.y, ct4.z};
    float rtv[4] = {ct4.y, ct4.z, ct4.w, rt_e};
    uint32_t buv[4] = {bu0, bu1, bu2, bu3};
    uint32_t bdv[4] = {bd0, bd1, bd2, bd3};
    uint32_t blv[4] = {bl0, bl1, bl2, bl3};
    uint32_t brv[4] = {br0, br1, br2, br3};

    float res[4];
#pragma unroll
    for (int i = 0; i < 4; i++) {
        float ur = u01(buv[i]);
        float dr = u01(bdv[i]);
        float lr = u01(blv[i]);
        float rr = u01(brv[i]);
        float s   = (ur + dr) + (lr + rr);
        float num = fmaf(upv[i], ur, fmaf(dnv[i], dr, fmaf(lfv[i], lr, rtv[i] * rr)));
        res[i] = __fdividef(num, s);
    }

    *reinterpret_cast<float4*>(out + base) = make_float4(res[0], res[1], res[2], res[3]);
}

extern "C" void kernel_launch(void* const* d_in, const int* in_sizes, int n_in,
                              void* d_out, int out_size) {
    const float* t = (const float*)d_in[0];
    float* out = (float*)d_out;
    (void)in_sizes; (void)n_in; (void)out_size;

    const uint32_t threads = 256;
    const uint32_t blocks = (N1 / 4u) / threads;   // 24576, exact
    neighbor_noiser_kernel<<<blocks, threads>>>(t, out);
}

// round 17
// speedup vs baseline: 1.0075x; 1.0075x over previous
#include <cuda_runtime.h>
#include <stdint.h>

// NeighborNoiser — partitionable threefry2x32, key (0,42), fold = x0^x1.
// R17 = R13 (best 248.3us) + divide-cancellation epilogue: the u01 scale
// factor 2^-23 and exponent-bias games cancel in num/den, so
//   res = (sum t_i * B_i) / (sum B_i),  B_i = (float)bits_i  (full 32-bit I2F).
// Deletes 4 IMAD.HI + 4 FADD per pixel, adds 4 I2F: net -4 slots/px.
// Accuracy: keeps low 9 bits JAX drops + 32->24b rounding => ~1e-7 rel err.
// Model: dur = slots/0.775 until alu pipe binds at ~241us (164 alu-ops/px).

#define N1 25165824u                    // 8*3*1024*1024

__device__ __forceinline__ uint32_t rotl(uint32_t v, const int d) {
    return __funnelshift_l(v, v, d);
}

#define RS(d) { x0 += x1; x1 = rotl(x1,(d)) ^ x0; }

// SHF-rotate threefry chain, IADD3-fused key schedule
__device__ __forceinline__ uint32_t tf_shf(uint32_t ctr) {
    const uint32_t ks1 = 42u, ks2 = 0x1BD11BDAu ^ 42u;
    uint32_t x1 = ctr + ks1;
    uint32_t x0 = x1;                               // round-1 add with x0 = 0
    x1 = rotl(x1,13) ^ x0;
    RS(15) RS(26) RS(6)
    x1 += ks2 + 1u;  x0 = x0 + x1 + ks1;  x1 = rotl(x1,17) ^ x0;
    RS(29) RS(16) RS(24)
    x1 += 2u;        x0 = x0 + x1 + ks2;  x1 = rotl(x1,13) ^ x0;
    RS(15) RS(26) RS(6)
    x1 += ks1 + 3u;  x0 = x0 + x1;        x1 = rotl(x1,17) ^ x0;   // ks0 = 0
    RS(29) RS(16) RS(24)
    x1 += ks2 + 4u;  x0 = x0 + x1 + ks1;  x1 = rotl(x1,13) ^ x0;
    RS(15) RS(26) RS(6)
    x1 += 5u;
    return (x0 + ks2) ^ x1;
}

__global__ __launch_bounds__(256, 6)
void neighbor_noiser_kernel(const float* __restrict__ t, float* __restrict__ out) {
    uint32_t gid  = blockIdx.x * blockDim.x + threadIdx.x;
    uint32_t base = gid * 4u;                   // 4 adjacent pixels in one row

    uint32_t plane = base >> 20;
    uint32_t pos   = base & 0xFFFFFu;
    uint32_t y     = pos >> 10;
    uint32_t x     = pos & 1023u;               // multiple of 4

    const float* p = t + ((size_t)plane << 20);
    uint32_t yu = (y == 0u)    ? 0u    : y - 1u;
    uint32_t yd = (y == 1023u) ? 1023u : y + 1u;
    const float* rowc = p + (y << 10);

    float4 up4 = __ldg((const float4*)(p + (yu << 10) + x));
    float4 dn4 = __ldg((const float4*)(p + (yd << 10) + x));
    float4 ct4 = __ldg((const float4*)(rowc + x));
    float lf_e = (x == 0u)     ? ct4.x : __ldg(rowc + x - 1u);
    float rt_e = (x == 1020u)  ? ct4.w : __ldg(rowc + x + 4u);

    // 16 independent SHF chains
    uint32_t bu0 = tf_shf(base);
    uint32_t bu1 = tf_shf(base + 1u);
    uint32_t bu2 = tf_shf(base + 2u);
    uint32_t bu3 = tf_shf(base + 3u);
    uint32_t bd0 = tf_shf(base + N1);
    uint32_t bd1 = tf_shf(base + N1 + 1u);
    uint32_t bd2 = tf_shf(base + N1 + 2u);
    uint32_t bd3 = tf_shf(base + N1 + 3u);
    uint32_t bl0 = tf_shf(base + 2u*N1);
    uint32_t bl1 = tf_shf(base + 2u*N1 + 1u);
    uint32_t bl2 = tf_shf(base + 2u*N1 + 2u);
    uint32_t bl3 = tf_shf(base + 2u*N1 + 3u);
    uint32_t br0 = tf_shf(base + 3u*N1);
    uint32_t br1 = tf_shf(base + 3u*N1 + 1u);
    uint32_t br2 = tf_shf(base + 3u*N1 + 2u);
    uint32_t br3 = tf_shf(base + 3u*N1 + 3u);

    float upv[4] = {up4.x, up4.y, up4.z, up4.w};
    float dnv[4] = {dn4.x, dn4.y, dn4.z, dn4.w};
    float lfv[4] = {lf_e,  ct4.x, ct4.y, ct4.z};
    float rtv[4] = {ct4.y, ct4.z, ct4.w, rt_e};
    uint32_t buv[4] = {bu0, bu1, bu2, bu3};
    uint32_t bdv[4] = {bd0, bd1, bd2, bd3};
    uint32_t blv[4] = {bl0, bl1, bl2, bl3};
    uint32_t brv[4] = {br0, br1, br2, br3};

    float res[4];
#pragma unroll
    for (int i = 0; i < 4; i++) {
        // scale factors cancel in the ratio: use full 32-bit bits as weights
        float ur = __uint2float_rn(buv[i]);
        float dr = __uint2float_rn(bdv[i]);
        float lr = __uint2float_rn(blv[i]);
        float rr = __uint2float_rn(brv[i]);
        float s   = (ur + dr) + (lr + rr);
        float num = fmaf(upv[i], ur, fmaf(dnv[i], dr, fmaf(lfv[i], lr, rtv[i] * rr)));
        res[i] = __fdividef(num, s);
    }

    *reinterpret_cast<float4*>(out + base) = make_float4(res[0], res[1], res[2], res[3]);
}

extern "C" void kernel_launch(void* const* d_in, const int* in_sizes, int n_in,
                              void* d_out, int out_size) {
    const float* t = (const float*)d_in[0];
    float* out = (float*)d_out;
    (void)in_sizes; (void)n_in; (void)out_size;

    const uint32_t threads = 256;
    const uint32_t blocks = (N1 / 4u) / threads;   // 24576, exact
    neighbor_noiser_kernel<<<blocks, threads>>>(t, out);
}